// round 1
// baseline (speedup 1.0000x reference)
#include <cuda_runtime.h>
#include <math.h>
#include <stdint.h>
#include <stddef.h>

// Problem constants (fixed by the reference setup_inputs)
#define BATCH  2
#define NTOK   4096
#define DMODEL 512
#define HEADS  8
#define HDIM   64
#define KNN    9
#define MROWS  (BATCH * NTOK)          // 8192

// Scratch (static __device__ arrays: allocation-free, harness-legal)
__device__ float g_qkv[(size_t)MROWS * 3 * DMODEL];   // 48 MB: full QKV projection
__device__ float g_attn[(size_t)MROWS * DMODEL];      // 16 MB: GELU(attention out)
__device__ int   g_nn[(size_t)MROWS * KNN];           // top-9 neighbor indices

// ---------------------------------------------------------------------------
// NT GEMM: C[m,n] = dot(A[m,:], B[n,:]) ; A: MxK row-major, B: NxK row-major.
// 128x128 block tile, BK=16, 256 threads, 8x8 micro-tile.
// Epilogue (bias != nullptr): C[m,n] += bias[n] + resid[m*N+n]
// Requires M%128==0, N%128==0, K%16==0 (true for all our shapes).
// ---------------------------------------------------------------------------
__global__ void __launch_bounds__(256) gemm_nt_kernel(
    const float* __restrict__ A, const float* __restrict__ B, float* __restrict__ C,
    int M, int N, int Kd,
    const float* __restrict__ bias, const float* __restrict__ resid)
{
    constexpr int BK = 16;
    __shared__ float As[BK][128];
    __shared__ float Bs[BK][128];

    const int bm  = blockIdx.y * 128;
    const int bn  = blockIdx.x * 128;
    const int tid = threadIdx.x;
    const int tx  = tid & 15;   // n direction (8 cols each)
    const int ty  = tid >> 4;   // m direction (8 rows each)

    float acc[8][8];
    #pragma unroll
    for (int i = 0; i < 8; i++)
        #pragma unroll
        for (int j = 0; j < 8; j++) acc[i][j] = 0.f;

    // global-load mapping: 512 float4 per tile / 256 threads = 2 each
    const int row0 = tid >> 2;          // 0..63
    const int c4   = (tid & 3) << 2;    // 0,4,8,12

    for (int k0 = 0; k0 < Kd; k0 += BK) {
        float4 a0 = *(const float4*)(A + (size_t)(bm + row0)      * Kd + k0 + c4);
        float4 a1 = *(const float4*)(A + (size_t)(bm + row0 + 64) * Kd + k0 + c4);
        float4 b0 = *(const float4*)(B + (size_t)(bn + row0)      * Kd + k0 + c4);
        float4 b1 = *(const float4*)(B + (size_t)(bn + row0 + 64) * Kd + k0 + c4);

        __syncthreads();  // previous compute done before smem overwrite
        As[c4+0][row0]    = a0.x; As[c4+1][row0]    = a0.y; As[c4+2][row0]    = a0.z; As[c4+3][row0]    = a0.w;
        As[c4+0][row0+64] = a1.x; As[c4+1][row0+64] = a1.y; As[c4+2][row0+64] = a1.z; As[c4+3][row0+64] = a1.w;
        Bs[c4+0][row0]    = b0.x; Bs[c4+1][row0]    = b0.y; Bs[c4+2][row0]    = b0.z; Bs[c4+3][row0]    = b0.w;
        Bs[c4+0][row0+64] = b1.x; Bs[c4+1][row0+64] = b1.y; Bs[c4+2][row0+64] = b1.z; Bs[c4+3][row0+64] = b1.w;
        __syncthreads();

        #pragma unroll
        for (int kk = 0; kk < BK; kk++) {
            float ar[8], br[8];
            *(float4*)(ar)     = *(const float4*)&As[kk][ty * 8];
            *(float4*)(ar + 4) = *(const float4*)&As[kk][ty * 8 + 4];
            *(float4*)(br)     = *(const float4*)&Bs[kk][tx * 8];
            *(float4*)(br + 4) = *(const float4*)&Bs[kk][tx * 8 + 4];
            #pragma unroll
            for (int i = 0; i < 8; i++)
                #pragma unroll
                for (int j = 0; j < 8; j++)
                    acc[i][j] = fmaf(ar[i], br[j], acc[i][j]);
        }
    }

    const bool epi = (bias != nullptr);
    #pragma unroll
    for (int i = 0; i < 8; i++) {
        const int m = bm + ty * 8 + i;
        #pragma unroll
        for (int jj = 0; jj < 8; jj += 4) {
            const int n = bn + tx * 8 + jj;
            float4 v = make_float4(acc[i][jj], acc[i][jj+1], acc[i][jj+2], acc[i][jj+3]);
            if (epi) {
                float4 r = *(const float4*)(resid + (size_t)m * N + n);
                v.x += bias[n+0] + r.x;
                v.y += bias[n+1] + r.y;
                v.z += bias[n+2] + r.z;
                v.w += bias[n+3] + r.w;
            }
            *(float4*)(C + (size_t)m * N + n) = v;
        }
    }
}

// ---------------------------------------------------------------------------
// k-NN top-9 (smallest squared distance, tie -> smaller index, self included).
// One warp per query row. Per-lane sorted top-9 in registers (static-index
// branchless insertion), then 9 rounds of warp argmin on packed (dist,idx).
// ---------------------------------------------------------------------------
__global__ void __launch_bounds__(256) knn_kernel(
    const float* __restrict__ coords, int* __restrict__ nn)
{
    const int warp = blockIdx.x * (blockDim.x >> 5) + (threadIdx.x >> 5);
    const int lane = threadIdx.x & 31;
    if (warp >= MROWS) return;
    const int b = warp / NTOK;
    const int n = warp - b * NTOK;

    const float2* cb = (const float2*)(coords + (size_t)b * NTOK * 2);
    const float2 qc = cb[n];

    float d9[KNN];
    int   i9[KNN];
    #pragma unroll
    for (int j = 0; j < KNN; j++) { d9[j] = 3.4e38f; i9[j] = 0x7fffffff; }

    for (int m = lane; m < NTOK; m += 32) {
        const float2 c = cb[m];
        const float dx = c.x - qc.x, dy = c.y - qc.y;
        const float d2 = dx * dx + dy * dy;
        if (d2 < d9[KNN - 1]) {
            // branchless insertion, all static register indices
            #pragma unroll
            for (int j = KNN - 1; j >= 1; j--) {
                const bool below_prev = d2 < d9[j - 1];
                const bool below_here = d2 < d9[j];   // pre-update value (high->low walk)
                const float nd = below_prev ? d9[j - 1] : (below_here ? d2 : d9[j]);
                const int   ni = below_prev ? i9[j - 1] : (below_here ? m  : i9[j]);
                d9[j] = nd; i9[j] = ni;
            }
            if (d2 < d9[0]) { d9[0] = d2; i9[0] = m; }
        }
    }

    // warp merge: 9 rounds of 64-bit argmin (float bits high, index low)
    #pragma unroll
    for (int j = 0; j < KNN; j++) {
        unsigned long long mykey =
            ((unsigned long long)__float_as_uint(d9[0]) << 32) | (unsigned)i9[0];
        unsigned long long k = mykey;
        #pragma unroll
        for (int s = 16; s; s >>= 1) {
            unsigned long long o = __shfl_xor_sync(0xffffffffu, k, s);
            k = (o < k) ? o : k;
        }
        if (k == mykey) {   // unique winner (indices are unique): pop my head
            #pragma unroll
            for (int t = 0; t < KNN - 1; t++) { d9[t] = d9[t + 1]; i9[t] = i9[t + 1]; }
            d9[KNN - 1] = 3.4e38f; i9[KNN - 1] = 0x7fffffff;
        }
        if (lane == 0) nn[(size_t)warp * KNN + j] = (int)(k & 0xffffffffu);
    }
}

// ---------------------------------------------------------------------------
// Attention over 9 neighbors, fused exact-erf GELU.
// One block per token (8192 blocks), one warp per head, 2 head-elems per lane.
// q = qkv[r, 0:512], k_j = qkv[b, idx_j, 512:1024], v_j = qkv[b, idx_j, 1024:1536]
// ---------------------------------------------------------------------------
__global__ void __launch_bounds__(256) attn_kernel(
    const float* __restrict__ qkv, const int* __restrict__ nn,
    float* __restrict__ out)
{
    const int r    = blockIdx.x;          // token row 0..8191
    const int b    = r >> 12;             // / 4096
    const int h    = threadIdx.x >> 5;    // head 0..7
    const int lane = threadIdx.x & 31;

    __shared__ int idx[KNN];
    if (threadIdx.x < KNN) idx[threadIdx.x] = nn[(size_t)r * KNN + threadIdx.x];
    __syncthreads();

    const size_t base = (size_t)b * NTOK * (3 * DMODEL);
    const float2 qv = *(const float2*)(qkv + (size_t)r * (3 * DMODEL) + h * HDIM + lane * 2);

    float logit[KNN];
    #pragma unroll
    for (int j = 0; j < KNN; j++) {
        const float2 kv = *(const float2*)(qkv + base + (size_t)idx[j] * (3 * DMODEL)
                                           + DMODEL + h * HDIM + lane * 2);
        float p = qv.x * kv.x + qv.y * kv.y;
        #pragma unroll
        for (int s = 16; s; s >>= 1) p += __shfl_xor_sync(0xffffffffu, p, s);
        logit[j] = p * 0.125f;   // 1/sqrt(64)
    }

    float mx = logit[0];
    #pragma unroll
    for (int j = 1; j < KNN; j++) mx = fmaxf(mx, logit[j]);
    float sum = 0.f;
    #pragma unroll
    for (int j = 0; j < KNN; j++) { logit[j] = __expf(logit[j] - mx); sum += logit[j]; }
    const float inv = 1.f / sum;

    float2 acc = make_float2(0.f, 0.f);
    #pragma unroll
    for (int j = 0; j < KNN; j++) {
        const float2 vv = *(const float2*)(qkv + base + (size_t)idx[j] * (3 * DMODEL)
                                           + 2 * DMODEL + h * HDIM + lane * 2);
        const float w = logit[j] * inv;
        acc.x = fmaf(w, vv.x, acc.x);
        acc.y = fmaf(w, vv.y, acc.y);
    }

    // exact (erf) GELU, fused here so the proj GEMM reads ready inputs
    acc.x = 0.5f * acc.x * (1.f + erff(acc.x * 0.70710678118654752f));
    acc.y = 0.5f * acc.y * (1.f + erff(acc.y * 0.70710678118654752f));

    *(float2*)(out + (size_t)r * DMODEL + h * HDIM + lane * 2) = acc;
}

// ---------------------------------------------------------------------------
// kernel_launch: x, coords, w_qkv, w_proj, b_proj  ->  out (fp32, B*N*D)
// ---------------------------------------------------------------------------
extern "C" void kernel_launch(void* const* d_in, const int* in_sizes, int n_in,
                              void* d_out, int out_size)
{
    const float* x      = (const float*)d_in[0];
    const float* coords = (const float*)d_in[1];
    const float* w_qkv  = (const float*)d_in[2];
    const float* w_proj = (const float*)d_in[3];
    const float* b_proj = (const float*)d_in[4];
    float* out = (float*)d_out;

    float* qkv;  float* attn;  int* nn;
    cudaGetSymbolAddress((void**)&qkv,  g_qkv);
    cudaGetSymbolAddress((void**)&attn, g_attn);
    cudaGetSymbolAddress((void**)&nn,   g_nn);

    // 1) full QKV projection: (8192 x 512) @ (1536 x 512)^T
    {
        dim3 grid((3 * DMODEL) / 128, MROWS / 128);
        gemm_nt_kernel<<<grid, 256>>>(x, w_qkv, qkv, MROWS, 3 * DMODEL, DMODEL,
                                      nullptr, nullptr);
    }
    // 2) k-NN top-9 indices (independent of 1; sequential is fine)
    knn_kernel<<<MROWS / 8, 256>>>(coords, nn);

    // 3) neighbor attention + GELU
    attn_kernel<<<MROWS, 256>>>(qkv, nn, attn);

    // 4) output projection + bias + residual: (8192 x 512) @ (512 x 512)^T
    {
        dim3 grid(DMODEL / 128, MROWS / 128);
        gemm_nt_kernel<<<grid, 256>>>(attn, w_proj, out, MROWS, DMODEL, DMODEL,
                                      b_proj, x);
    }
}

// round 3
// speedup vs baseline: 2.2996x; 2.2996x over previous
#include <cuda_runtime.h>
#include <math.h>
#include <stdint.h>
#include <stddef.h>

// Problem constants (fixed by the reference setup_inputs)
#define BATCH  2
#define NTOK   4096
#define DMODEL 512
#define HEADS  8
#define HDIM   64
#define KNN    9
#define MROWS  (BATCH * NTOK)          // 8192

// Scratch (static __device__ arrays: allocation-free, harness-legal)
__device__ float g_qkv[(size_t)MROWS * 3 * DMODEL];   // 48 MB: full QKV projection
__device__ float g_attn[(size_t)MROWS * DMODEL];      // 16 MB: GELU(attention out)
__device__ int   g_nn[(size_t)MROWS * KNN];           // top-9 neighbor indices

// ===========================================================================
// Helpers: cp.async + tf32 mma.sync (base sm_103 ISA — no tcgen05 available
// through this toolchain, which targets sm_103 without the 'a' feature set)
// ===========================================================================
__device__ __forceinline__ void cp_async16(float* smem, const float* g) {
    uint32_t s = (uint32_t)__cvta_generic_to_shared(smem);
    asm volatile("cp.async.cg.shared.global [%0], [%1], 16;" :: "r"(s), "l"(g));
}
#define CP_COMMIT() asm volatile("cp.async.commit_group;" ::: "memory")
#define CP_WAIT1()  asm volatile("cp.async.wait_group 1;" ::: "memory")
#define CP_WAIT0()  asm volatile("cp.async.wait_group 0;" ::: "memory")

__device__ __forceinline__ void mma_tf32(float* d, const float* a, const float* b) {
    asm volatile(
        "mma.sync.aligned.m16n8k8.row.col.f32.tf32.tf32.f32 "
        "{%0,%1,%2,%3}, {%4,%5,%6,%7}, {%8,%9}, {%0,%1,%2,%3};"
        : "+f"(d[0]), "+f"(d[1]), "+f"(d[2]), "+f"(d[3])
        : "r"(__float_as_uint(a[0])), "r"(__float_as_uint(a[1])),
          "r"(__float_as_uint(a[2])), "r"(__float_as_uint(a[3])),
          "r"(__float_as_uint(b[0])), "r"(__float_as_uint(b[1])));
}

// Bank-conflict-free swizzle for 16-float (64B) rows.
// s(m) = (m ^ (m>>2)) & 3 makes (m&1, s(m)) injective over any 8 consecutive
// aligned rows -> fragment LDS and float4 fills are conflict-free.
__device__ __forceinline__ int swz(int m, int k) {
    int s = (m ^ (m >> 2)) & 3;
    return m * 16 + ((((k >> 2) ^ s) & 3) << 2) + (k & 3);
}

// ===========================================================================
// tf32 tensor-core NT GEMM: C[m,n] = dot(A[m,:], B[n,:])
//   A: MxK row-major fp32, B: NxK row-major fp32, C: MxN fp32
//   CTA 128x128, BK=16, cp.async double buffer, warp grid 4x2 (tile 32x64).
//   Epilogue (bias != nullptr): C += bias[n] + resid[m*N+n]
//   Requires M%128==0, N%128==0, K%16==0.
// ===========================================================================
__global__ void __launch_bounds__(256, 2) gemm_mma_tf32(
    const float* __restrict__ A, const float* __restrict__ B, float* __restrict__ C,
    int M, int N, int Kd,
    const float* __restrict__ bias, const float* __restrict__ resid)
{
    constexpr int BM = 128, BN = 128, BK = 16;
    __shared__ __align__(16) float sA[2][BM * BK];
    __shared__ __align__(16) float sB[2][BN * BK];

    const int tid  = threadIdx.x;
    const int warp = tid >> 5;
    const int lane = tid & 31;
    const int wm   = warp & 3;        // 0..3 -> m block of 32
    const int wn   = warp >> 2;       // 0..1 -> n block of 64
    const int r4   = lane >> 2;       // groupID
    const int c4   = lane & 3;        // threadID_in_group
    const int bm   = blockIdx.y * BM;
    const int bn   = blockIdx.x * BN;

    // fill mapping: 2 slots/thread, slot -> (row, 4-float group)
    const int frow = tid >> 2;        // 0..63 (+64 for i=1)
    const int fcg  = tid & 3;

    float acc[2][8][4];
    #pragma unroll
    for (int i = 0; i < 2; i++)
        #pragma unroll
        for (int j = 0; j < 8; j++)
            #pragma unroll
            for (int q = 0; q < 4; q++) acc[i][j][q] = 0.f;

    const int T = Kd >> 4;   // BK = 16

    // prologue: load tile 0 into stage 0
    #pragma unroll
    for (int i = 0; i < 2; ++i) {
        const int row = frow + 64 * i;
        const int so  = swz(row, fcg * 4);
        cp_async16(&sA[0][so], A + (size_t)(bm + row) * Kd + fcg * 4);
        cp_async16(&sB[0][so], B + (size_t)(bn + row) * Kd + fcg * 4);
    }
    CP_COMMIT();

    for (int t = 0; t < T; ++t) {
        const int cur = t & 1;
        if (t + 1 < T) {
            const int k0 = (t + 1) << 4;
            #pragma unroll
            for (int i = 0; i < 2; ++i) {
                const int row = frow + 64 * i;
                const int so  = swz(row, fcg * 4);
                cp_async16(&sA[cur ^ 1][so], A + (size_t)(bm + row) * Kd + k0 + fcg * 4);
                cp_async16(&sB[cur ^ 1][so], B + (size_t)(bn + row) * Kd + k0 + fcg * 4);
            }
            CP_COMMIT();
            CP_WAIT1();
        } else {
            CP_WAIT0();
        }
        __syncthreads();

        const float* sAc = sA[cur];
        const float* sBc = sB[cur];
        #pragma unroll
        for (int ks = 0; ks < 2; ++ks) {
            const int kb = ks * 8;
            float a[2][4], bf[8][2];
            #pragma unroll
            for (int am = 0; am < 2; ++am) {
                const int m0 = wm * 32 + am * 16 + r4;
                a[am][0] = sAc[swz(m0,     kb + c4)];
                a[am][1] = sAc[swz(m0 + 8, kb + c4)];
                a[am][2] = sAc[swz(m0,     kb + c4 + 4)];
                a[am][3] = sAc[swz(m0 + 8, kb + c4 + 4)];
            }
            #pragma unroll
            for (int nb = 0; nb < 8; ++nb) {
                const int n0 = wn * 64 + nb * 8 + r4;
                bf[nb][0] = sBc[swz(n0, kb + c4)];
                bf[nb][1] = sBc[swz(n0, kb + c4 + 4)];
            }
            #pragma unroll
            for (int am = 0; am < 2; ++am)
                #pragma unroll
                for (int nb = 0; nb < 8; ++nb)
                    mma_tf32(acc[am][nb], a[am], bf[nb]);
        }
        __syncthreads();
    }

    // epilogue: direct float2 stores (C frag: rows r4/r4+8, cols 2*c4, 2*c4+1)
    const bool has_epi = (bias != nullptr);
    #pragma unroll
    for (int am = 0; am < 2; ++am) {
        const int m0 = bm + wm * 32 + am * 16 + r4;
        #pragma unroll
        for (int nb = 0; nb < 8; ++nb) {
            const int n0 = bn + wn * 64 + nb * 8 + c4 * 2;
            float2 v01 = make_float2(acc[am][nb][0], acc[am][nb][1]);
            float2 v23 = make_float2(acc[am][nb][2], acc[am][nb][3]);
            if (has_epi) {
                const float2 bz = *(const float2*)(bias + n0);
                const float2 r0 = *(const float2*)(resid + (size_t)m0 * N + n0);
                const float2 r1 = *(const float2*)(resid + (size_t)(m0 + 8) * N + n0);
                v01.x += bz.x + r0.x;  v01.y += bz.y + r0.y;
                v23.x += bz.x + r1.x;  v23.y += bz.y + r1.y;
            }
            *(float2*)(C + (size_t)m0 * N + n0)       = v01;
            *(float2*)(C + (size_t)(m0 + 8) * N + n0) = v23;
        }
    }
}

// ---------------------------------------------------------------------------
// k-NN top-9 (smallest squared distance, tie -> smaller index, self included).
// One warp per query row; register top-9 insertion + warp argmin merge.
// ---------------------------------------------------------------------------
__global__ void __launch_bounds__(256) knn_kernel(
    const float* __restrict__ coords, int* __restrict__ nn)
{
    const int warp = blockIdx.x * (blockDim.x >> 5) + (threadIdx.x >> 5);
    const int lane = threadIdx.x & 31;
    if (warp >= MROWS) return;
    const int b = warp / NTOK;
    const int n = warp - b * NTOK;

    const float2* cb = (const float2*)(coords + (size_t)b * NTOK * 2);
    const float2 qc = cb[n];

    float d9[KNN];
    int   i9[KNN];
    #pragma unroll
    for (int j = 0; j < KNN; j++) { d9[j] = 3.4e38f; i9[j] = 0x7fffffff; }

    for (int m = lane; m < NTOK; m += 32) {
        const float2 c = cb[m];
        const float dx = c.x - qc.x, dy = c.y - qc.y;
        const float d2 = dx * dx + dy * dy;
        if (d2 < d9[KNN - 1]) {
            #pragma unroll
            for (int j = KNN - 1; j >= 1; j--) {
                const bool below_prev = d2 < d9[j - 1];
                const bool below_here = d2 < d9[j];
                const float nd = below_prev ? d9[j - 1] : (below_here ? d2 : d9[j]);
                const int   ni = below_prev ? i9[j - 1] : (below_here ? m  : i9[j]);
                d9[j] = nd; i9[j] = ni;
            }
            if (d2 < d9[0]) { d9[0] = d2; i9[0] = m; }
        }
    }

    #pragma unroll
    for (int j = 0; j < KNN; j++) {
        unsigned long long mykey =
            ((unsigned long long)__float_as_uint(d9[0]) << 32) | (unsigned)i9[0];
        unsigned long long k = mykey;
        #pragma unroll
        for (int s = 16; s; s >>= 1) {
            unsigned long long o = __shfl_xor_sync(0xffffffffu, k, s);
            k = (o < k) ? o : k;
        }
        if (k == mykey) {
            #pragma unroll
            for (int t = 0; t < KNN - 1; t++) { d9[t] = d9[t + 1]; i9[t] = i9[t + 1]; }
            d9[KNN - 1] = 3.4e38f; i9[KNN - 1] = 0x7fffffff;
        }
        if (lane == 0) nn[(size_t)warp * KNN + j] = (int)(k & 0xffffffffu);
    }
}

// ---------------------------------------------------------------------------
// Attention over 9 neighbors, fused exact-erf GELU.
// One block per token, one warp per head, 2 head-elems per lane.
// ---------------------------------------------------------------------------
__global__ void __launch_bounds__(256) attn_kernel(
    const float* __restrict__ qkv, const int* __restrict__ nn,
    float* __restrict__ out)
{
    const int r    = blockIdx.x;
    const int b    = r >> 12;
    const int h    = threadIdx.x >> 5;
    const int lane = threadIdx.x & 31;

    __shared__ int idx[KNN];
    if (threadIdx.x < KNN) idx[threadIdx.x] = nn[(size_t)r * KNN + threadIdx.x];
    __syncthreads();

    const size_t base = (size_t)b * NTOK * (3 * DMODEL);
    const float2 qv = *(const float2*)(qkv + (size_t)r * (3 * DMODEL) + h * HDIM + lane * 2);

    float logit[KNN];
    #pragma unroll
    for (int j = 0; j < KNN; j++) {
        const float2 kv = *(const float2*)(qkv + base + (size_t)idx[j] * (3 * DMODEL)
                                           + DMODEL + h * HDIM + lane * 2);
        float p = qv.x * kv.x + qv.y * kv.y;
        #pragma unroll
        for (int s = 16; s; s >>= 1) p += __shfl_xor_sync(0xffffffffu, p, s);
        logit[j] = p * 0.125f;
    }

    float mx = logit[0];
    #pragma unroll
    for (int j = 1; j < KNN; j++) mx = fmaxf(mx, logit[j]);
    float sum = 0.f;
    #pragma unroll
    for (int j = 0; j < KNN; j++) { logit[j] = __expf(logit[j] - mx); sum += logit[j]; }
    const float inv = 1.f / sum;

    float2 acc = make_float2(0.f, 0.f);
    #pragma unroll
    for (int j = 0; j < KNN; j++) {
        const float2 vv = *(const float2*)(qkv + base + (size_t)idx[j] * (3 * DMODEL)
                                           + 2 * DMODEL + h * HDIM + lane * 2);
        const float w = logit[j] * inv;
        acc.x = fmaf(w, vv.x, acc.x);
        acc.y = fmaf(w, vv.y, acc.y);
    }

    acc.x = 0.5f * acc.x * (1.f + erff(acc.x * 0.70710678118654752f));
    acc.y = 0.5f * acc.y * (1.f + erff(acc.y * 0.70710678118654752f));

    *(float2*)(out + (size_t)r * DMODEL + h * HDIM + lane * 2) = acc;
}

// ---------------------------------------------------------------------------
// kernel_launch: x, coords, w_qkv, w_proj, b_proj  ->  out (fp32, B*N*D)
// ---------------------------------------------------------------------------
extern "C" void kernel_launch(void* const* d_in, const int* in_sizes, int n_in,
                              void* d_out, int out_size)
{
    const float* x      = (const float*)d_in[0];
    const float* coords = (const float*)d_in[1];
    const float* w_qkv  = (const float*)d_in[2];
    const float* w_proj = (const float*)d_in[3];
    const float* b_proj = (const float*)d_in[4];
    float* out = (float*)d_out;

    float* qkv;  float* attn;  int* nn;
    cudaGetSymbolAddress((void**)&qkv,  g_qkv);
    cudaGetSymbolAddress((void**)&attn, g_attn);
    cudaGetSymbolAddress((void**)&nn,   g_nn);

    // 1) full QKV projection: (8192 x 512) @ (1536 x 512)^T  [tf32 mma.sync]
    {
        dim3 grid((3 * DMODEL) / 128, MROWS / 128);
        gemm_mma_tf32<<<grid, 256>>>(x, w_qkv, qkv, MROWS, 3 * DMODEL, DMODEL,
                                     nullptr, nullptr);
    }
    // 2) k-NN top-9 indices
    knn_kernel<<<MROWS / 8, 256>>>(coords, nn);

    // 3) neighbor attention + GELU
    attn_kernel<<<MROWS, 256>>>(qkv, nn, attn);

    // 4) output projection + bias + residual: (8192 x 512) @ (512 x 512)^T
    {
        dim3 grid(DMODEL / 128, MROWS / 128);
        gemm_mma_tf32<<<grid, 256>>>(attn, w_proj, out, MROWS, DMODEL, DMODEL,
                                     b_proj, x);
    }
}

// round 4
// speedup vs baseline: 2.3974x; 1.0425x over previous
#include <cuda_runtime.h>
#include <math.h>
#include <stdint.h>
#include <stddef.h>

// Problem constants (fixed by the reference setup_inputs)
#define BATCH  2
#define NTOK   4096
#define DMODEL 512
#define HEADS  8
#define HDIM   64
#define KNN    9
#define MROWS  (BATCH * NTOK)          // 8192

// Scratch (static __device__ arrays: allocation-free, harness-legal)
__device__ float g_qkv[(size_t)MROWS * 3 * DMODEL];   // 48 MB: full QKV projection
__device__ float g_attn[(size_t)MROWS * DMODEL];      // 16 MB: GELU(attention out)
__device__ int   g_nn[(size_t)MROWS * KNN];           // top-9 neighbor indices

// ===========================================================================
// Helpers: cp.async + tf32 mma.sync (base sm_103 ISA — tcgen05 is rejected by
// this toolchain's sm_103 target, so legacy HMMA is the tensor path)
// ===========================================================================
__device__ __forceinline__ void cp_async16(float* smem, const float* g) {
    uint32_t s = (uint32_t)__cvta_generic_to_shared(smem);
    asm volatile("cp.async.cg.shared.global [%0], [%1], 16;" :: "r"(s), "l"(g));
}
#define CP_COMMIT() asm volatile("cp.async.commit_group;" ::: "memory")
#define CP_WAIT1()  asm volatile("cp.async.wait_group 1;" ::: "memory")
#define CP_WAIT0()  asm volatile("cp.async.wait_group 0;" ::: "memory")

__device__ __forceinline__ void mma_tf32(float* d, const float* a, const float* b) {
    asm volatile(
        "mma.sync.aligned.m16n8k8.row.col.f32.tf32.tf32.f32 "
        "{%0,%1,%2,%3}, {%4,%5,%6,%7}, {%8,%9}, {%0,%1,%2,%3};"
        : "+f"(d[0]), "+f"(d[1]), "+f"(d[2]), "+f"(d[3])
        : "r"(__float_as_uint(a[0])), "r"(__float_as_uint(a[1])),
          "r"(__float_as_uint(a[2])), "r"(__float_as_uint(a[3])),
          "r"(__float_as_uint(b[0])), "r"(__float_as_uint(b[1])));
}

// Bank-conflict-free swizzle for 16-float (64B) rows.
__device__ __forceinline__ int swz(int m, int k) {
    int s = (m ^ (m >> 2)) & 3;
    return m * 16 + ((((k >> 2) ^ s) & 3) << 2) + (k & 3);
}

// ===========================================================================
// GEMM body: C[m,n] = dot(A[m,:], B[n,:]) for one 128x128 tile at (bm, bn).
// 3-stage cp.async ring, ONE __syncthreads per k-tile, warp grid 4x2 (32x64).
// Epilogue (bias != nullptr): C += bias[n] + resid[m*N+n].
// ===========================================================================
__device__ __forceinline__ void gemm_body(
    const float* __restrict__ A, const float* __restrict__ B, float* __restrict__ C,
    int N, int Kd, const float* __restrict__ bias, const float* __restrict__ resid,
    int bm, int bn, float* __restrict__ sA, float* __restrict__ sB)   // [3][2048] each
{
    const int tid  = threadIdx.x;
    const int warp = tid >> 5;
    const int lane = tid & 31;
    const int wm   = warp & 3;        // m block of 32
    const int wn   = warp >> 2;       // n block of 64
    const int r4   = lane >> 2;
    const int c4   = lane & 3;

    // fill mapping: 2 slots/thread per array
    const int frow = tid >> 2;        // 0..63 (+64 for i=1)
    const int fcg  = tid & 3;
    const int so0  = swz(frow, fcg * 4);
    const int so1  = swz(frow + 64, fcg * 4);
    const float* gA0 = A + (size_t)(bm + frow) * Kd + fcg * 4;
    const float* gA1 = A + (size_t)(bm + frow + 64) * Kd + fcg * 4;
    const float* gB0 = B + (size_t)(bn + frow) * Kd + fcg * 4;
    const float* gB1 = B + (size_t)(bn + frow + 64) * Kd + fcg * 4;

    float acc[2][8][4];
    #pragma unroll
    for (int i = 0; i < 2; i++)
        #pragma unroll
        for (int j = 0; j < 8; j++)
            #pragma unroll
            for (int q = 0; q < 4; q++) acc[i][j][q] = 0.f;

    const int T = Kd >> 4;   // BK = 16; T >= 2 for all our shapes

    // prologue: tiles 0, 1 into stages 0, 1
    #pragma unroll
    for (int s = 0; s < 2; ++s) {
        const int k0 = s << 4;
        cp_async16(sA + s * 2048 + so0, gA0 + k0);
        cp_async16(sA + s * 2048 + so1, gA1 + k0);
        cp_async16(sB + s * 2048 + so0, gB0 + k0);
        cp_async16(sB + s * 2048 + so1, gB1 + k0);
        CP_COMMIT();
    }

    int stage = 0;
    for (int t = 0; t < T; ++t) {
        if (t + 1 < T) CP_WAIT1(); else CP_WAIT0();
        __syncthreads();

        if (t + 2 < T) {
            const int k0 = (t + 2) << 4;
            int s2 = stage + 2; if (s2 >= 3) s2 -= 3;
            cp_async16(sA + s2 * 2048 + so0, gA0 + k0);
            cp_async16(sA + s2 * 2048 + so1, gA1 + k0);
            cp_async16(sB + s2 * 2048 + so0, gB0 + k0);
            cp_async16(sB + s2 * 2048 + so1, gB1 + k0);
            CP_COMMIT();
        }

        const float* sAc = sA + stage * 2048;
        const float* sBc = sB + stage * 2048;
        #pragma unroll
        for (int ks = 0; ks < 2; ++ks) {
            const int kb = ks * 8;
            float a[2][4], bf[8][2];
            #pragma unroll
            for (int am = 0; am < 2; ++am) {
                const int m0 = wm * 32 + am * 16 + r4;
                a[am][0] = sAc[swz(m0,     kb + c4)];
                a[am][1] = sAc[swz(m0 + 8, kb + c4)];
                a[am][2] = sAc[swz(m0,     kb + c4 + 4)];
                a[am][3] = sAc[swz(m0 + 8, kb + c4 + 4)];
            }
            #pragma unroll
            for (int nb = 0; nb < 8; ++nb) {
                const int n0 = wn * 64 + nb * 8 + r4;
                bf[nb][0] = sBc[swz(n0, kb + c4)];
                bf[nb][1] = sBc[swz(n0, kb + c4 + 4)];
            }
            #pragma unroll
            for (int am = 0; am < 2; ++am)
                #pragma unroll
                for (int nb = 0; nb < 8; ++nb)
                    mma_tf32(acc[am][nb], a[am], bf[nb]);
        }
        if (++stage == 3) stage = 0;
    }

    // epilogue: direct float2 stores (C frag rows r4/r4+8, cols 2*c4, 2*c4+1)
    const bool has_epi = (bias != nullptr);
    #pragma unroll
    for (int am = 0; am < 2; ++am) {
        const int m0 = bm + wm * 32 + am * 16 + r4;
        #pragma unroll
        for (int nb = 0; nb < 8; ++nb) {
            const int n0 = bn + wn * 64 + nb * 8 + c4 * 2;
            float2 v01 = make_float2(acc[am][nb][0], acc[am][nb][1]);
            float2 v23 = make_float2(acc[am][nb][2], acc[am][nb][3]);
            if (has_epi) {
                const float2 bz = *(const float2*)(bias + n0);
                const float2 r0 = *(const float2*)(resid + (size_t)m0 * N + n0);
                const float2 r1 = *(const float2*)(resid + (size_t)(m0 + 8) * N + n0);
                v01.x += bz.x + r0.x;  v01.y += bz.y + r0.y;
                v23.x += bz.x + r1.x;  v23.y += bz.y + r1.y;
            }
            *(float2*)(C + (size_t)m0 * N + n0)       = v01;
            *(float2*)(C + (size_t)(m0 + 8) * N + n0) = v23;
        }
    }
}

// ---------------------------------------------------------------------------
// k-NN body: one warp per query row (register top-9 + warp argmin merge).
// ---------------------------------------------------------------------------
__device__ __forceinline__ void knn_body(
    const float* __restrict__ coords, int* __restrict__ nn, int qwarp)
{
    const int lane = threadIdx.x & 31;
    const int b = qwarp / NTOK;
    const int n = qwarp - b * NTOK;

    const float2* cb = (const float2*)(coords + (size_t)b * NTOK * 2);
    const float2 qc = cb[n];

    float d9[KNN];
    int   i9[KNN];
    #pragma unroll
    for (int j = 0; j < KNN; j++) { d9[j] = 3.4e38f; i9[j] = 0x7fffffff; }

    for (int m = lane; m < NTOK; m += 32) {
        const float2 c = cb[m];
        const float dx = c.x - qc.x, dy = c.y - qc.y;
        const float d2 = dx * dx + dy * dy;
        if (d2 < d9[KNN - 1]) {
            #pragma unroll
            for (int j = KNN - 1; j >= 1; j--) {
                const bool below_prev = d2 < d9[j - 1];
                const bool below_here = d2 < d9[j];
                const float nd = below_prev ? d9[j - 1] : (below_here ? d2 : d9[j]);
                const int   ni = below_prev ? i9[j - 1] : (below_here ? m  : i9[j]);
                d9[j] = nd; i9[j] = ni;
            }
            if (d2 < d9[0]) { d9[0] = d2; i9[0] = m; }
        }
    }

    #pragma unroll
    for (int j = 0; j < KNN; j++) {
        unsigned long long mykey =
            ((unsigned long long)__float_as_uint(d9[0]) << 32) | (unsigned)i9[0];
        unsigned long long k = mykey;
        #pragma unroll
        for (int s = 16; s; s >>= 1) {
            unsigned long long o = __shfl_xor_sync(0xffffffffu, k, s);
            k = (o < k) ? o : k;
        }
        if (k == mykey) {
            #pragma unroll
            for (int t = 0; t < KNN - 1; t++) { d9[t] = d9[t + 1]; i9[t] = i9[t + 1]; }
            d9[KNN - 1] = 3.4e38f; i9[KNN - 1] = 0x7fffffff;
        }
        if (lane == 0) nn[(size_t)qwarp * KNN + j] = (int)(k & 0xffffffffu);
    }
}

// ===========================================================================
// Fused launch 1: blocks [0, 768) = QKV GEMM tiles (12 x 64 flattened),
//                 blocks [768, 1792) = kNN (8 query warps per block).
// ===========================================================================
#define QKV_GEMM_BLOCKS 768   // (3*DMODEL/128) * (MROWS/128)

__global__ void __launch_bounds__(256, 2) qkv_knn_kernel(
    const float* __restrict__ x, const float* __restrict__ w_qkv,
    float* __restrict__ qkv,
    const float* __restrict__ coords, int* __restrict__ nn)
{
    __shared__ __align__(16) float sA[3 * 2048];
    __shared__ __align__(16) float sB[3 * 2048];

    if (blockIdx.x < QKV_GEMM_BLOCKS) {
        const int bn = (blockIdx.x % 12) * 128;
        const int bm = (blockIdx.x / 12) * 128;
        gemm_body(x, w_qkv, qkv, 3 * DMODEL, DMODEL, nullptr, nullptr,
                  bm, bn, sA, sB);
    } else {
        const int qwarp = (blockIdx.x - QKV_GEMM_BLOCKS) * 8 + (threadIdx.x >> 5);
        knn_body(coords, nn, qwarp);
    }
}

// Launch 3: output projection + bias + residual (2D grid of 128x128 tiles)
__global__ void __launch_bounds__(256, 2) proj_kernel(
    const float* __restrict__ A, const float* __restrict__ B, float* __restrict__ C,
    int N, int Kd, const float* __restrict__ bias, const float* __restrict__ resid)
{
    __shared__ __align__(16) float sA[3 * 2048];
    __shared__ __align__(16) float sB[3 * 2048];
    gemm_body(A, B, C, N, Kd, bias, resid,
              blockIdx.y * 128, blockIdx.x * 128, sA, sB);
}

// ---------------------------------------------------------------------------
// Attention over 9 neighbors, fused exact-erf GELU.
// One block per token, one warp per head, 2 head-elems per lane.
// ---------------------------------------------------------------------------
__global__ void __launch_bounds__(256) attn_kernel(
    const float* __restrict__ qkv, const int* __restrict__ nn,
    float* __restrict__ out)
{
    const int r    = blockIdx.x;
    const int b    = r >> 12;
    const int h    = threadIdx.x >> 5;
    const int lane = threadIdx.x & 31;

    __shared__ int idx[KNN];
    if (threadIdx.x < KNN) idx[threadIdx.x] = nn[(size_t)r * KNN + threadIdx.x];
    __syncthreads();

    const size_t base = (size_t)b * NTOK * (3 * DMODEL);
    const float2 qv = *(const float2*)(qkv + (size_t)r * (3 * DMODEL) + h * HDIM + lane * 2);

    float logit[KNN];
    #pragma unroll
    for (int j = 0; j < KNN; j++) {
        const float2 kv = *(const float2*)(qkv + base + (size_t)idx[j] * (3 * DMODEL)
                                           + DMODEL + h * HDIM + lane * 2);
        float p = qv.x * kv.x + qv.y * kv.y;
        #pragma unroll
        for (int s = 16; s; s >>= 1) p += __shfl_xor_sync(0xffffffffu, p, s);
        logit[j] = p * 0.125f;
    }

    float mx = logit[0];
    #pragma unroll
    for (int j = 1; j < KNN; j++) mx = fmaxf(mx, logit[j]);
    float sum = 0.f;
    #pragma unroll
    for (int j = 0; j < KNN; j++) { logit[j] = __expf(logit[j] - mx); sum += logit[j]; }
    const float inv = 1.f / sum;

    float2 acc = make_float2(0.f, 0.f);
    #pragma unroll
    for (int j = 0; j < KNN; j++) {
        const float2 vv = *(const float2*)(qkv + base + (size_t)idx[j] * (3 * DMODEL)
                                           + 2 * DMODEL + h * HDIM + lane * 2);
        const float w = logit[j] * inv;
        acc.x = fmaf(w, vv.x, acc.x);
        acc.y = fmaf(w, vv.y, acc.y);
    }

    acc.x = 0.5f * acc.x * (1.f + erff(acc.x * 0.70710678118654752f));
    acc.y = 0.5f * acc.y * (1.f + erff(acc.y * 0.70710678118654752f));

    *(float2*)(out + (size_t)r * DMODEL + h * HDIM + lane * 2) = acc;
}

// ---------------------------------------------------------------------------
// kernel_launch: x, coords, w_qkv, w_proj, b_proj  ->  out (fp32, B*N*D)
// ---------------------------------------------------------------------------
extern "C" void kernel_launch(void* const* d_in, const int* in_sizes, int n_in,
                              void* d_out, int out_size)
{
    const float* x      = (const float*)d_in[0];
    const float* coords = (const float*)d_in[1];
    const float* w_qkv  = (const float*)d_in[2];
    const float* w_proj = (const float*)d_in[3];
    const float* b_proj = (const float*)d_in[4];
    float* out = (float*)d_out;

    float* qkv;  float* attn;  int* nn;
    cudaGetSymbolAddress((void**)&qkv,  g_qkv);
    cudaGetSymbolAddress((void**)&attn, g_attn);
    cudaGetSymbolAddress((void**)&nn,   g_nn);

    // 1) QKV projection (768 GEMM blocks) + kNN (1024 blocks), one launch
    qkv_knn_kernel<<<QKV_GEMM_BLOCKS + MROWS / 8, 256>>>(x, w_qkv, qkv, coords, nn);

    // 2) neighbor attention + GELU
    attn_kernel<<<MROWS, 256>>>(qkv, nn, attn);

    // 3) output projection + bias + residual: (8192 x 512) @ (512 x 512)^T
    {
        dim3 grid(DMODEL / 128, MROWS / 128);
        proj_kernel<<<grid, 256>>>(attn, w_proj, out, DMODEL, DMODEL, b_proj, x);
    }
}

// round 5
// speedup vs baseline: 5.3898x; 2.2482x over previous
#include <cuda_runtime.h>
#include <cuda_bf16.h>
#include <math.h>
#include <stdint.h>
#include <stddef.h>

// Problem constants (fixed by the reference setup_inputs)
#define BATCH  2
#define NTOK   4096
#define DMODEL 512
#define HEADS  8
#define HDIM   64
#define KNN    9
#define MROWS  (BATCH * NTOK)          // 8192
#define GRID   64
#define CELLS  (GRID * GRID)
#define CELLSZ 1.5625f                 // 100/64
#define INVCELL 0.64f                  // 64/100

// Scratch (static __device__ arrays: allocation-free, harness-legal)
__device__ float          g_qkv[(size_t)MROWS * 3 * DMODEL];     // fp32 QKV
__device__ __nv_bfloat16  g_attnb[(size_t)MROWS * DMODEL];       // bf16 GELU(attn)
__device__ __nv_bfloat16  g_xb[(size_t)MROWS * DMODEL];          // bf16 x
__device__ __nv_bfloat16  g_wqb[(size_t)3 * DMODEL * DMODEL];    // bf16 w_qkv
__device__ __nv_bfloat16  g_wpb[(size_t)DMODEL * DMODEL];        // bf16 w_proj
__device__ int            g_nn[(size_t)MROWS * KNN];
__device__ int            g_cellstart[BATCH * (CELLS + 1)];
__device__ float2         g_scoord[BATCH * NTOK];
__device__ int            g_sidx[BATCH * NTOK];

// ===========================================================================
// PTX helpers (base sm_103 ISA: cp.async + ldmatrix + bf16 mma.sync)
// ===========================================================================
__device__ __forceinline__ void cp16(uint32_t saddr, const void* g) {
    asm volatile("cp.async.cg.shared.global [%0], [%1], 16;" :: "r"(saddr), "l"(g));
}
#define CP_COMMIT() asm volatile("cp.async.commit_group;" ::: "memory")
#define CP_WAIT1()  asm volatile("cp.async.wait_group 1;" ::: "memory")
#define CP_WAIT0()  asm volatile("cp.async.wait_group 0;" ::: "memory")

__device__ __forceinline__ void ldsm4(uint32_t* r, uint32_t addr) {
    asm volatile("ldmatrix.sync.aligned.m8n8.x4.shared.b16 {%0,%1,%2,%3}, [%4];"
                 : "=r"(r[0]), "=r"(r[1]), "=r"(r[2]), "=r"(r[3]) : "r"(addr));
}
__device__ __forceinline__ void mma_bf16(float* d, const uint32_t* a, const uint32_t* b) {
    asm volatile(
        "mma.sync.aligned.m16n8k16.row.col.f32.bf16.bf16.f32 "
        "{%0,%1,%2,%3},{%4,%5,%6,%7},{%8,%9},{%0,%1,%2,%3};"
        : "+f"(d[0]), "+f"(d[1]), "+f"(d[2]), "+f"(d[3])
        : "r"(a[0]), "r"(a[1]), "r"(a[2]), "r"(a[3]), "r"(b[0]), "r"(b[1]));
}
// 64B-row swizzle selector: chunk_phys = chunk ^ swzs(row) is ldmatrix-conflict-free
__device__ __forceinline__ int swzs(int row) { return (row ^ (row >> 2)) & 3; }

// ===========================================================================
// bf16 tensor-core NT GEMM body: C[m,n] = dot(A[m,:], B[n,:]) (fp32 accum)
//   A: MxK bf16 row-major, B: NxK bf16 row-major, C: MxN fp32.
//   CTA 128x128, BK=32, 3-stage cp.async ring, warp grid 4x2 (32x64 tiles),
//   all fragments via ldmatrix.x4. Epilogue: C += bias[n] + resid[m*N+n].
// ===========================================================================
__device__ __forceinline__ void gemm_body_bf16(
    const __nv_bfloat16* __restrict__ A, const __nv_bfloat16* __restrict__ B,
    float* __restrict__ C, int N, int Kd,
    const float* __restrict__ bias, const float* __restrict__ resid,
    int bm, int bn, unsigned char* smem)   // smem: 3 stages x (8KB A + 8KB B)
{
    const int tid  = threadIdx.x;
    const int warp = tid >> 5;
    const int lane = tid & 31;
    const int wm   = warp & 3;        // m block of 32
    const int wn   = warp >> 2;       // n block of 64
    const uint32_t sbase = (uint32_t)__cvta_generic_to_shared(smem);

    // cp.async fill mapping: 512 16B chunks per array per stage, 2 per thread
    const int r0 = tid >> 2,          c0 = tid & 3;
    const int r1 = (tid + 256) >> 2,  c1 = tid & 3;
    const uint32_t d0 = r0 * 64 + ((c0 ^ swzs(r0)) << 4);
    const uint32_t d1 = r1 * 64 + ((c1 ^ swzs(r1)) << 4);
    const __nv_bfloat16* gA0 = A + (size_t)(bm + r0) * Kd + c0 * 8;
    const __nv_bfloat16* gA1 = A + (size_t)(bm + r1) * Kd + c1 * 8;
    const __nv_bfloat16* gB0 = B + (size_t)(bn + r0) * Kd + c0 * 8;
    const __nv_bfloat16* gB1 = B + (size_t)(bn + r1) * Kd + c1 * 8;

    // ldmatrix lane addressing (A: 2 m16 tiles; B: 4 n16 pairs)
    const int l7 = lane & 7;
    int rowA[2], swA[2];
    #pragma unroll
    for (int am = 0; am < 2; am++) {
        const int row = wm * 32 + am * 16 + ((lane >> 3) & 1) * 8 + l7;
        rowA[am] = row * 64;  swA[am] = swzs(row);
    }
    const int cselA = lane >> 4;
    int rowB[4], swB[4];
    #pragma unroll
    for (int bp = 0; bp < 4; bp++) {
        const int row = wn * 64 + bp * 16 + ((lane >> 4) << 3) + l7;
        rowB[bp] = row * 64;  swB[bp] = swzs(row);
    }
    const int cselB = (lane >> 3) & 1;

    float acc[2][8][4];
    #pragma unroll
    for (int i = 0; i < 2; i++)
        #pragma unroll
        for (int j = 0; j < 8; j++)
            #pragma unroll
            for (int q = 0; q < 4; q++) acc[i][j][q] = 0.f;

    const int T = Kd >> 5;   // BK = 32

    #pragma unroll
    for (int s = 0; s < 2; ++s) {     // prologue: stages 0,1
        const int k0 = s << 5;
        const uint32_t sa = sbase + s * 16384, sb = sa + 8192;
        cp16(sa + d0, gA0 + k0);  cp16(sa + d1, gA1 + k0);
        cp16(sb + d0, gB0 + k0);  cp16(sb + d1, gB1 + k0);
        CP_COMMIT();
    }

    int stage = 0;
    for (int t = 0; t < T; ++t) {
        if (t + 1 < T) CP_WAIT1(); else CP_WAIT0();
        __syncthreads();

        if (t + 2 < T) {
            int s2 = stage + 2; if (s2 >= 3) s2 -= 3;
            const int k0 = (t + 2) << 5;
            const uint32_t sa = sbase + s2 * 16384, sb = sa + 8192;
            cp16(sa + d0, gA0 + k0);  cp16(sa + d1, gA1 + k0);
            cp16(sb + d0, gB0 + k0);  cp16(sb + d1, gB1 + k0);
            CP_COMMIT();
        }

        const uint32_t sa = sbase + stage * 16384, sb = sa + 8192;
        #pragma unroll
        for (int g = 0; g < 2; ++g) {     // two k16 steps per k-tile
            uint32_t af[2][4], bf[4][4];
            #pragma unroll
            for (int am = 0; am < 2; am++)
                ldsm4(af[am], sa + rowA[am] + ((((g << 1) | cselA) ^ swA[am]) << 4));
            #pragma unroll
            for (int bp = 0; bp < 4; bp++)
                ldsm4(bf[bp], sb + rowB[bp] + ((((g << 1) | cselB) ^ swB[bp]) << 4));
            #pragma unroll
            for (int am = 0; am < 2; am++)
                #pragma unroll
                for (int nb = 0; nb < 8; nb++)
                    mma_bf16(acc[am][nb], af[am], &bf[nb >> 1][(nb & 1) << 1]);
        }
        if (++stage == 3) stage = 0;
    }

    // epilogue: direct float2 stores (rows r4/r4+8, cols 2*c4, 2*c4+1)
    const int r4 = lane >> 2, c4 = lane & 3;
    const bool has_epi = (bias != nullptr);
    #pragma unroll
    for (int am = 0; am < 2; ++am) {
        const int m0 = bm + wm * 32 + am * 16 + r4;
        #pragma unroll
        for (int nb = 0; nb < 8; ++nb) {
            const int n0 = bn + wn * 64 + nb * 8 + c4 * 2;
            float2 v01 = make_float2(acc[am][nb][0], acc[am][nb][1]);
            float2 v23 = make_float2(acc[am][nb][2], acc[am][nb][3]);
            if (has_epi) {
                const float2 bz = *(const float2*)(bias + n0);
                const float2 q0 = *(const float2*)(resid + (size_t)m0 * N + n0);
                const float2 q1 = *(const float2*)(resid + (size_t)(m0 + 8) * N + n0);
                v01.x += bz.x + q0.x;  v01.y += bz.y + q0.y;
                v23.x += bz.x + q1.x;  v23.y += bz.y + q1.y;
            }
            *(float2*)(C + (size_t)m0 * N + n0)       = v01;
            *(float2*)(C + (size_t)(m0 + 8) * N + n0) = v23;
        }
    }
}

// ===========================================================================
// prep kernel: blocks 0..1 build the per-batch spatial grid (histogram +
// prefix scan + scatter); remaining blocks convert fp32 -> bf16.
// ===========================================================================
__global__ void __launch_bounds__(1024) prep_kernel(
    const float* __restrict__ x, const float* __restrict__ coords,
    const float* __restrict__ w_qkv, const float* __restrict__ w_proj)
{
    if (blockIdx.x < BATCH) {
        const int b = blockIdx.x;
        __shared__ int cnt[CELLS];
        __shared__ int part[1024];
        const int t = threadIdx.x;
        #pragma unroll
        for (int i = t; i < CELLS; i += 1024) cnt[i] = 0;
        __syncthreads();

        const float2* cb = (const float2*)coords + (size_t)b * NTOK;
        int pcid[4]; float2 pc[4];
        #pragma unroll
        for (int j = 0; j < 4; j++) {
            const int p = t + j * 1024;
            const float2 c = cb[p];
            const int cx = min(GRID - 1, max(0, (int)(c.x * INVCELL)));
            const int cy = min(GRID - 1, max(0, (int)(c.y * INVCELL)));
            pcid[j] = cy * GRID + cx;  pc[j] = c;
            atomicAdd(&cnt[pcid[j]], 1);
        }
        __syncthreads();

        const int c0 = cnt[t*4], c1 = cnt[t*4+1], c2 = cnt[t*4+2], c3 = cnt[t*4+3];
        const int lsum = c0 + c1 + c2 + c3;
        part[t] = lsum;
        __syncthreads();
        for (int off = 1; off < 1024; off <<= 1) {
            const int v = (t >= off) ? part[t - off] : 0;
            __syncthreads();
            part[t] += v;
            __syncthreads();
        }
        const int excl = part[t] - lsum;
        const int s0 = excl, s1 = excl + c0, s2 = s1 + c1, s3 = s2 + c2;
        cnt[t*4] = s0; cnt[t*4+1] = s1; cnt[t*4+2] = s2; cnt[t*4+3] = s3;
        int* csg = g_cellstart + b * (CELLS + 1);
        csg[t*4] = s0; csg[t*4+1] = s1; csg[t*4+2] = s2; csg[t*4+3] = s3;
        if (t == 1023) csg[CELLS] = NTOK;
        __syncthreads();

        #pragma unroll
        for (int j = 0; j < 4; j++) {
            const int pos = atomicAdd(&cnt[pcid[j]], 1);
            g_scoord[b * NTOK + pos] = pc[j];
            g_sidx[b * NTOK + pos]   = t + j * 1024;
        }
    } else {
        // fp32 -> bf16 conversion (x, w_qkv, w_proj), float4 granularity
        constexpr long XQ = (long)MROWS * DMODEL / 4;
        constexpr long WQ = (long)3 * DMODEL * DMODEL / 4;
        constexpr long WP = (long)DMODEL * DMODEL / 4;
        const long nb = gridDim.x - BATCH;
        for (long i = (long)(blockIdx.x - BATCH) * 1024 + threadIdx.x;
             i < XQ + WQ + WP; i += nb * 1024) {
            const float4* src; uint2* dst; long off;
            if (i < XQ)            { src = (const float4*)x;      dst = (uint2*)g_xb;  off = i; }
            else if (i < XQ + WQ)  { src = (const float4*)w_qkv;  dst = (uint2*)g_wqb; off = i - XQ; }
            else                   { src = (const float4*)w_proj; dst = (uint2*)g_wpb; off = i - XQ - WQ; }
            const float4 v = src[off];
            const __nv_bfloat162 lo = __floats2bfloat162_rn(v.x, v.y);
            const __nv_bfloat162 hi = __floats2bfloat162_rn(v.z, v.w);
            uint2 o; o.x = *(const uint32_t*)&lo; o.y = *(const uint32_t*)&hi;
            dst[off] = o;
        }
    }
}

// ===========================================================================
// grid kNN query: one thread per query; exact top-9 via ring expansion with
// cell-box lower-bound pruning. Ring r+1 min dist >= r*CELLSZ (stop bound).
// ===========================================================================
__device__ __forceinline__ void scan_cell(
    int X, int Y, float qx, float qy,
    const int* __restrict__ cs, const float2* __restrict__ sc,
    const int* __restrict__ si,
    float (&d9)[KNN], int (&i9)[KNN], float& dmax, int& imax)
{
    const float lx = X * CELLSZ, ly = Y * CELLSZ;
    const float ddx = fmaxf(0.f, fmaxf(lx - qx, qx - (lx + CELLSZ)));
    const float ddy = fmaxf(0.f, fmaxf(ly - qy, qy - (ly + CELLSZ)));
    if (ddx * ddx + ddy * ddy >= dmax) return;
    const int cid = Y * GRID + X;
    const int s1 = cs[cid + 1];
    for (int s = cs[cid]; s < s1; ++s) {
        const float2 p = sc[s];
        const float dx = p.x - qx, dy = p.y - qy;
        const float d2 = dx * dx + dy * dy;
        if (d2 < dmax) {
            const int idx = si[s];
            #pragma unroll
            for (int j = 0; j < KNN; j++)
                if (j == imax) { d9[j] = d2; i9[j] = idx; }
            dmax = d9[0]; imax = 0;
            #pragma unroll
            for (int j = 1; j < KNN; j++)
                if (d9[j] > dmax) { dmax = d9[j]; imax = j; }
        }
    }
}

__device__ __forceinline__ void knn_query(const float* __restrict__ coords, int q)
{
    const int b = q >> 12, n = q & (NTOK - 1);
    const float2 qc = ((const float2*)coords)[(size_t)b * NTOK + n];
    const float qx = qc.x, qy = qc.y;
    const int cx = min(GRID - 1, max(0, (int)(qx * INVCELL)));
    const int cy = min(GRID - 1, max(0, (int)(qy * INVCELL)));
    const int*    cs = g_cellstart + b * (CELLS + 1);
    const float2* sc = g_scoord + b * NTOK;
    const int*    si = g_sidx + b * NTOK;

    float d9[KNN]; int i9[KNN];
    #pragma unroll
    for (int j = 0; j < KNN; j++) { d9[j] = 3.4e38f; i9[j] = 0; }
    float dmax = 3.4e38f; int imax = 0;

    for (int r = 0; r < GRID; ++r) {
        const int xlo = max(cx - r, 0), xhi = min(cx + r, GRID - 1);
        if (r == 0) {
            scan_cell(cx, cy, qx, qy, cs, sc, si, d9, i9, dmax, imax);
        } else {
            if (cy - r >= 0)
                for (int X = xlo; X <= xhi; X++)
                    scan_cell(X, cy - r, qx, qy, cs, sc, si, d9, i9, dmax, imax);
            if (cy + r <= GRID - 1)
                for (int X = xlo; X <= xhi; X++)
                    scan_cell(X, cy + r, qx, qy, cs, sc, si, d9, i9, dmax, imax);
            const int yl = max(cy - r + 1, 0), yh = min(cy + r - 1, GRID - 1);
            if (cx - r >= 0)
                for (int Y = yl; Y <= yh; Y++)
                    scan_cell(cx - r, Y, qx, qy, cs, sc, si, d9, i9, dmax, imax);
            if (cx + r <= GRID - 1)
                for (int Y = yl; Y <= yh; Y++)
                    scan_cell(cx + r, Y, qx, qy, cs, sc, si, d9, i9, dmax, imax);
        }
        const float rs = r * CELLSZ;
        if (rs * rs >= dmax) break;     // next ring cannot beat current 9th
    }
    #pragma unroll
    for (int j = 0; j < KNN; j++) g_nn[(size_t)q * KNN + j] = i9[j];
}

// ===========================================================================
// Fused launch: blocks [0,32) = kNN query (256 queries each, scheduled first
// so they hide under the GEMM); blocks [32, 800) = QKV GEMM tiles.
// ===========================================================================
#define KNN_BLOCKS 32

__global__ void __launch_bounds__(256, 2) qkv_knn_kernel(const float* __restrict__ coords)
{
    __shared__ __align__(128) unsigned char smem[49152];
    if (blockIdx.x < KNN_BLOCKS) {
        knn_query(coords, blockIdx.x * 256 + threadIdx.x);
    } else {
        const int idx = blockIdx.x - KNN_BLOCKS;
        gemm_body_bf16(g_xb, g_wqb, g_qkv, 3 * DMODEL, DMODEL, nullptr, nullptr,
                       (idx / 12) * 128, (idx % 12) * 128, smem);
    }
}

__global__ void __launch_bounds__(256, 2) proj_kernel(
    float* __restrict__ C, const float* __restrict__ bias, const float* __restrict__ resid)
{
    __shared__ __align__(128) unsigned char smem[49152];
    gemm_body_bf16(g_attnb, g_wpb, C, DMODEL, DMODEL, bias, resid,
                   blockIdx.y * 128, blockIdx.x * 128, smem);
}

// ---------------------------------------------------------------------------
// Attention over 9 neighbors, fused exact-erf GELU, bf16 output for proj.
// One block per token, one warp per head, 2 head-elems per lane.
// ---------------------------------------------------------------------------
__global__ void __launch_bounds__(256) attn_kernel()
{
    const float* __restrict__ qkv = g_qkv;
    const int r    = blockIdx.x;
    const int b    = r >> 12;
    const int h    = threadIdx.x >> 5;
    const int lane = threadIdx.x & 31;

    __shared__ int idx[KNN];
    if (threadIdx.x < KNN) idx[threadIdx.x] = g_nn[(size_t)r * KNN + threadIdx.x];
    __syncthreads();

    const size_t base = (size_t)b * NTOK * (3 * DMODEL);
    const float2 qv = *(const float2*)(qkv + (size_t)r * (3 * DMODEL) + h * HDIM + lane * 2);

    float logit[KNN];
    #pragma unroll
    for (int j = 0; j < KNN; j++) {
        const float2 kv = *(const float2*)(qkv + base + (size_t)idx[j] * (3 * DMODEL)
                                           + DMODEL + h * HDIM + lane * 2);
        float p = qv.x * kv.x + qv.y * kv.y;
        #pragma unroll
        for (int s = 16; s; s >>= 1) p += __shfl_xor_sync(0xffffffffu, p, s);
        logit[j] = p * 0.125f;
    }

    float mx = logit[0];
    #pragma unroll
    for (int j = 1; j < KNN; j++) mx = fmaxf(mx, logit[j]);
    float sum = 0.f;
    #pragma unroll
    for (int j = 0; j < KNN; j++) { logit[j] = __expf(logit[j] - mx); sum += logit[j]; }
    const float inv = 1.f / sum;

    float2 acc = make_float2(0.f, 0.f);
    #pragma unroll
    for (int j = 0; j < KNN; j++) {
        const float2 vv = *(const float2*)(qkv + base + (size_t)idx[j] * (3 * DMODEL)
                                           + 2 * DMODEL + h * HDIM + lane * 2);
        const float w = logit[j] * inv;
        acc.x = fmaf(w, vv.x, acc.x);
        acc.y = fmaf(w, vv.y, acc.y);
    }

    acc.x = 0.5f * acc.x * (1.f + erff(acc.x * 0.70710678118654752f));
    acc.y = 0.5f * acc.y * (1.f + erff(acc.y * 0.70710678118654752f));

    *(__nv_bfloat162*)(g_attnb + (size_t)r * DMODEL + h * HDIM + lane * 2)
        = __floats2bfloat162_rn(acc.x, acc.y);
}

// ---------------------------------------------------------------------------
// kernel_launch: x, coords, w_qkv, w_proj, b_proj  ->  out (fp32, B*N*D)
// ---------------------------------------------------------------------------
extern "C" void kernel_launch(void* const* d_in, const int* in_sizes, int n_in,
                              void* d_out, int out_size)
{
    const float* x      = (const float*)d_in[0];
    const float* coords = (const float*)d_in[1];
    const float* w_qkv  = (const float*)d_in[2];
    const float* w_proj = (const float*)d_in[3];
    const float* b_proj = (const float*)d_in[4];
    float* out = (float*)d_out;

    // 1) grid build (2 blocks) + fp32->bf16 conversion (640 blocks)
    prep_kernel<<<BATCH + 640, 1024>>>(x, coords, w_qkv, w_proj);

    // 2) kNN query (32 blocks, first) + QKV GEMM (768 blocks), one launch
    qkv_knn_kernel<<<KNN_BLOCKS + 768, 256>>>(coords);

    // 3) neighbor attention + GELU (bf16 out)
    attn_kernel<<<MROWS, 256>>>();

    // 4) output projection + bias + residual
    {
        dim3 grid(DMODEL / 128, MROWS / 128);
        proj_kernel<<<grid, 256>>>(out, b_proj, x);
    }
}

// round 6
// speedup vs baseline: 5.4525x; 1.0116x over previous
#include <cuda_runtime.h>
#include <cuda_bf16.h>
#include <math.h>
#include <stdint.h>
#include <stddef.h>

// Problem constants (fixed by the reference setup_inputs)
#define BATCH  2
#define NTOK   4096
#define DMODEL 512
#define HEADS  8
#define HDIM   64
#define KNN    9
#define MROWS  (BATCH * NTOK)          // 8192
#define GRID   64
#define CELLS  (GRID * GRID)
#define CELLSZ 1.5625f                 // 100/64
#define INVCELL 0.64f                  // 64/100

// Scratch (static __device__ arrays: allocation-free, harness-legal)
__device__ float          g_q[(size_t)MROWS * DMODEL];           // fp32 Q
__device__ __nv_bfloat16  g_kvb[(size_t)MROWS * 2 * DMODEL];     // bf16 K|V
__device__ __nv_bfloat16  g_attnb[(size_t)MROWS * DMODEL];       // bf16 GELU(attn)
__device__ __nv_bfloat16  g_xb[(size_t)MROWS * DMODEL];          // bf16 x
__device__ __nv_bfloat16  g_wqb[(size_t)3 * DMODEL * DMODEL];    // bf16 w_qkv
__device__ __nv_bfloat16  g_wpb[(size_t)DMODEL * DMODEL];        // bf16 w_proj
__device__ int            g_nn[(size_t)MROWS * KNN];
__device__ int            g_cellstart[BATCH * (CELLS + 1)];
__device__ float2         g_scoord[BATCH * NTOK];
__device__ int            g_sidx[BATCH * NTOK];

// ===========================================================================
// PTX helpers (base sm_103 ISA: cp.async + ldmatrix + bf16 mma.sync)
// ===========================================================================
__device__ __forceinline__ void cp16(uint32_t saddr, const void* g) {
    asm volatile("cp.async.cg.shared.global [%0], [%1], 16;" :: "r"(saddr), "l"(g));
}
#define CP_COMMIT() asm volatile("cp.async.commit_group;" ::: "memory")
#define CP_WAIT2()  asm volatile("cp.async.wait_group 2;" ::: "memory")
#define CP_WAIT1()  asm volatile("cp.async.wait_group 1;" ::: "memory")
#define CP_WAIT0()  asm volatile("cp.async.wait_group 0;" ::: "memory")

__device__ __forceinline__ void ldsm4(uint32_t* r, uint32_t addr) {
    asm volatile("ldmatrix.sync.aligned.m8n8.x4.shared.b16 {%0,%1,%2,%3}, [%4];"
                 : "=r"(r[0]), "=r"(r[1]), "=r"(r[2]), "=r"(r[3]) : "r"(addr));
}
__device__ __forceinline__ void mma_bf16(float* d, const uint32_t* a, const uint32_t* b) {
    asm volatile(
        "mma.sync.aligned.m16n8k16.row.col.f32.bf16.bf16.f32 "
        "{%0,%1,%2,%3},{%4,%5,%6,%7},{%8,%9},{%0,%1,%2,%3};"
        : "+f"(d[0]), "+f"(d[1]), "+f"(d[2]), "+f"(d[3])
        : "r"(a[0]), "r"(a[1]), "r"(a[2]), "r"(a[3]), "r"(b[0]), "r"(b[1]));
}
__device__ __forceinline__ int swzs(int row) { return (row ^ (row >> 2)) & 3; }

// ===========================================================================
// bf16 tensor-core NT GEMM body (fp32 accum), 4-stage cp.async ring.
// CTA 128x128, BK=32, warp grid 4x2 (32x64), ldmatrix fragments.
// MODE 0: C fp32.  MODE 1: C fp32 += bias[n] + resid[m*N+n].
// MODE 2: QKV split — cols [0,512) fp32 -> g_q; cols [512,1536) bf16 -> g_kvb.
// smem: 4 stages x (8KB A + 8KB B) = 64KB dynamic.
// ===========================================================================
template <int MODE>
__device__ __forceinline__ void gemm_body_bf16(
    const __nv_bfloat16* __restrict__ A, const __nv_bfloat16* __restrict__ B,
    float* __restrict__ C, int N, int Kd,
    const float* __restrict__ bias, const float* __restrict__ resid,
    int bm, int bn, unsigned char* smem)
{
    const int tid  = threadIdx.x;
    const int warp = tid >> 5;
    const int lane = tid & 31;
    const int wm   = warp & 3;
    const int wn   = warp >> 2;
    const uint32_t sbase = (uint32_t)__cvta_generic_to_shared(smem);

    // cp.async fill mapping: 512 16B chunks per array per stage, 2 per thread
    const int r0 = tid >> 2,          c0 = tid & 3;
    const int r1 = (tid + 256) >> 2,  c1 = tid & 3;
    const uint32_t d0 = r0 * 64 + ((c0 ^ swzs(r0)) << 4);
    const uint32_t d1 = r1 * 64 + ((c1 ^ swzs(r1)) << 4);
    const __nv_bfloat16* gA0 = A + (size_t)(bm + r0) * Kd + c0 * 8;
    const __nv_bfloat16* gA1 = A + (size_t)(bm + r1) * Kd + c1 * 8;
    const __nv_bfloat16* gB0 = B + (size_t)(bn + r0) * Kd + c0 * 8;
    const __nv_bfloat16* gB1 = B + (size_t)(bn + r1) * Kd + c1 * 8;

    // ldmatrix lane addressing
    const int l7 = lane & 7;
    int rowA[2], swA[2];
    #pragma unroll
    for (int am = 0; am < 2; am++) {
        const int row = wm * 32 + am * 16 + ((lane >> 3) & 1) * 8 + l7;
        rowA[am] = row * 64;  swA[am] = swzs(row);
    }
    const int cselA = lane >> 4;
    int rowB[4], swB[4];
    #pragma unroll
    for (int bp = 0; bp < 4; bp++) {
        const int row = wn * 64 + bp * 16 + ((lane >> 4) << 3) + l7;
        rowB[bp] = row * 64;  swB[bp] = swzs(row);
    }
    const int cselB = (lane >> 3) & 1;

    float acc[2][8][4];
    #pragma unroll
    for (int i = 0; i < 2; i++)
        #pragma unroll
        for (int j = 0; j < 8; j++)
            #pragma unroll
            for (int q = 0; q < 4; q++) acc[i][j][q] = 0.f;

    const int T = Kd >> 5;   // BK = 32; T >= 4 for all our shapes

    #pragma unroll
    for (int s = 0; s < 3; ++s) {     // prologue: tiles 0..2 -> stages 0..2
        const int k0 = s << 5;
        const uint32_t sa = sbase + s * 16384, sb = sa + 8192;
        cp16(sa + d0, gA0 + k0);  cp16(sa + d1, gA1 + k0);
        cp16(sb + d0, gB0 + k0);  cp16(sb + d1, gB1 + k0);
        CP_COMMIT();
    }

    for (int t = 0; t < T; ++t) {
        if (t + 3 <= T) CP_WAIT2();
        else if (t + 2 == T) CP_WAIT1();
        else CP_WAIT0();
        __syncthreads();

        if (t + 3 < T) {
            const int s2 = (t + 3) & 3;
            const int k0 = (t + 3) << 5;
            const uint32_t sa = sbase + s2 * 16384, sb = sa + 8192;
            cp16(sa + d0, gA0 + k0);  cp16(sa + d1, gA1 + k0);
            cp16(sb + d0, gB0 + k0);  cp16(sb + d1, gB1 + k0);
            CP_COMMIT();
        }

        const uint32_t sa = sbase + (t & 3) * 16384, sb = sa + 8192;
        #pragma unroll
        for (int g = 0; g < 2; ++g) {
            uint32_t af[2][4], bf[4][4];
            #pragma unroll
            for (int am = 0; am < 2; am++)
                ldsm4(af[am], sa + rowA[am] + ((((g << 1) | cselA) ^ swA[am]) << 4));
            #pragma unroll
            for (int bp = 0; bp < 4; bp++)
                ldsm4(bf[bp], sb + rowB[bp] + ((((g << 1) | cselB) ^ swB[bp]) << 4));
            #pragma unroll
            for (int am = 0; am < 2; am++)
                #pragma unroll
                for (int nb = 0; nb < 8; nb++)
                    mma_bf16(acc[am][nb], af[am], &bf[nb >> 1][(nb & 1) << 1]);
        }
    }

    // ---- epilogue ----
    const int r4 = lane >> 2, c4 = lane & 3;
    #pragma unroll
    for (int am = 0; am < 2; ++am) {
        const int m0 = bm + wm * 32 + am * 16 + r4;
        #pragma unroll
        for (int nb = 0; nb < 8; ++nb) {
            const int n0 = bn + wn * 64 + nb * 8 + c4 * 2;
            float2 v01 = make_float2(acc[am][nb][0], acc[am][nb][1]);
            float2 v23 = make_float2(acc[am][nb][2], acc[am][nb][3]);
            if (MODE == 1) {
                const float2 bz = *(const float2*)(bias + n0);
                const float2 q0 = *(const float2*)(resid + (size_t)m0 * N + n0);
                const float2 q1 = *(const float2*)(resid + (size_t)(m0 + 8) * N + n0);
                v01.x += bz.x + q0.x;  v01.y += bz.y + q0.y;
                v23.x += bz.x + q1.x;  v23.y += bz.y + q1.y;
            }
            if (MODE == 2) {
                if (bn < DMODEL) {   // Q block (uniform per CTA)
                    *(float2*)(g_q + (size_t)m0 * DMODEL + n0)       = v01;
                    *(float2*)(g_q + (size_t)(m0 + 8) * DMODEL + n0) = v23;
                } else {             // K|V block -> bf16
                    const int nc = n0 - DMODEL;
                    *(__nv_bfloat162*)(g_kvb + (size_t)m0 * (2 * DMODEL) + nc)
                        = __floats2bfloat162_rn(v01.x, v01.y);
                    *(__nv_bfloat162*)(g_kvb + (size_t)(m0 + 8) * (2 * DMODEL) + nc)
                        = __floats2bfloat162_rn(v23.x, v23.y);
                }
            } else {
                *(float2*)(C + (size_t)m0 * N + n0)       = v01;
                *(float2*)(C + (size_t)(m0 + 8) * N + n0) = v23;
            }
        }
    }
}

// ===========================================================================
// prep kernel: blocks 0..1 build the per-batch spatial grid; rest convert
// fp32 -> bf16 (x, w_qkv, w_proj).
// ===========================================================================
__global__ void __launch_bounds__(1024) prep_kernel(
    const float* __restrict__ x, const float* __restrict__ coords,
    const float* __restrict__ w_qkv, const float* __restrict__ w_proj)
{
    if (blockIdx.x < BATCH) {
        const int b = blockIdx.x;
        __shared__ int cnt[CELLS];
        __shared__ int part[1024];
        const int t = threadIdx.x;
        #pragma unroll
        for (int i = t; i < CELLS; i += 1024) cnt[i] = 0;
        __syncthreads();

        const float2* cb = (const float2*)coords + (size_t)b * NTOK;
        int pcid[4]; float2 pc[4];
        #pragma unroll
        for (int j = 0; j < 4; j++) {
            const int p = t + j * 1024;
            const float2 c = cb[p];
            const int cx = min(GRID - 1, max(0, (int)(c.x * INVCELL)));
            const int cy = min(GRID - 1, max(0, (int)(c.y * INVCELL)));
            pcid[j] = cy * GRID + cx;  pc[j] = c;
            atomicAdd(&cnt[pcid[j]], 1);
        }
        __syncthreads();

        const int c0 = cnt[t*4], c1 = cnt[t*4+1], c2 = cnt[t*4+2], c3 = cnt[t*4+3];
        const int lsum = c0 + c1 + c2 + c3;
        part[t] = lsum;
        __syncthreads();
        for (int off = 1; off < 1024; off <<= 1) {
            const int v = (t >= off) ? part[t - off] : 0;
            __syncthreads();
            part[t] += v;
            __syncthreads();
        }
        const int excl = part[t] - lsum;
        const int s0 = excl, s1 = excl + c0, s2 = s1 + c1, s3 = s2 + c2;
        cnt[t*4] = s0; cnt[t*4+1] = s1; cnt[t*4+2] = s2; cnt[t*4+3] = s3;
        int* csg = g_cellstart + b * (CELLS + 1);
        csg[t*4] = s0; csg[t*4+1] = s1; csg[t*4+2] = s2; csg[t*4+3] = s3;
        if (t == 1023) csg[CELLS] = NTOK;
        __syncthreads();

        #pragma unroll
        for (int j = 0; j < 4; j++) {
            const int pos = atomicAdd(&cnt[pcid[j]], 1);
            g_scoord[b * NTOK + pos] = pc[j];
            g_sidx[b * NTOK + pos]   = t + j * 1024;
        }
    } else {
        constexpr long XQ = (long)MROWS * DMODEL / 4;
        constexpr long WQ = (long)3 * DMODEL * DMODEL / 4;
        constexpr long WP = (long)DMODEL * DMODEL / 4;
        const long nb = gridDim.x - BATCH;
        for (long i = (long)(blockIdx.x - BATCH) * 1024 + threadIdx.x;
             i < XQ + WQ + WP; i += nb * 1024) {
            const float4* src; uint2* dst; long off;
            if (i < XQ)            { src = (const float4*)x;      dst = (uint2*)g_xb;  off = i; }
            else if (i < XQ + WQ)  { src = (const float4*)w_qkv;  dst = (uint2*)g_wqb; off = i - XQ; }
            else                   { src = (const float4*)w_proj; dst = (uint2*)g_wpb; off = i - XQ - WQ; }
            const float4 v = src[off];
            const __nv_bfloat162 lo = __floats2bfloat162_rn(v.x, v.y);
            const __nv_bfloat162 hi = __floats2bfloat162_rn(v.z, v.w);
            uint2 o; o.x = *(const uint32_t*)&lo; o.y = *(const uint32_t*)&hi;
            dst[off] = o;
        }
    }
}

// ===========================================================================
// grid kNN query: one thread per query; exact top-9 via ring expansion.
// ===========================================================================
__device__ __forceinline__ void scan_cell(
    int X, int Y, float qx, float qy,
    const int* __restrict__ cs, const float2* __restrict__ sc,
    const int* __restrict__ si,
    float (&d9)[KNN], int (&i9)[KNN], float& dmax, int& imax)
{
    const float lx = X * CELLSZ, ly = Y * CELLSZ;
    const float ddx = fmaxf(0.f, fmaxf(lx - qx, qx - (lx + CELLSZ)));
    const float ddy = fmaxf(0.f, fmaxf(ly - qy, qy - (ly + CELLSZ)));
    if (ddx * ddx + ddy * ddy >= dmax) return;
    const int cid = Y * GRID + X;
    const int s1 = cs[cid + 1];
    for (int s = cs[cid]; s < s1; ++s) {
        const float2 p = sc[s];
        const float dx = p.x - qx, dy = p.y - qy;
        const float d2 = dx * dx + dy * dy;
        if (d2 < dmax) {
            const int idx = si[s];
            #pragma unroll
            for (int j = 0; j < KNN; j++)
                if (j == imax) { d9[j] = d2; i9[j] = idx; }
            dmax = d9[0]; imax = 0;
            #pragma unroll
            for (int j = 1; j < KNN; j++)
                if (d9[j] > dmax) { dmax = d9[j]; imax = j; }
        }
    }
}

__device__ __forceinline__ void knn_query(const float* __restrict__ coords, int q)
{
    const int b = q >> 12, n = q & (NTOK - 1);
    const float2 qc = ((const float2*)coords)[(size_t)b * NTOK + n];
    const float qx = qc.x, qy = qc.y;
    const int cx = min(GRID - 1, max(0, (int)(qx * INVCELL)));
    const int cy = min(GRID - 1, max(0, (int)(qy * INVCELL)));
    const int*    cs = g_cellstart + b * (CELLS + 1);
    const float2* sc = g_scoord + b * NTOK;
    const int*    si = g_sidx + b * NTOK;

    float d9[KNN]; int i9[KNN];
    #pragma unroll
    for (int j = 0; j < KNN; j++) { d9[j] = 3.4e38f; i9[j] = 0; }
    float dmax = 3.4e38f; int imax = 0;

    for (int r = 0; r < GRID; ++r) {
        const int xlo = max(cx - r, 0), xhi = min(cx + r, GRID - 1);
        if (r == 0) {
            scan_cell(cx, cy, qx, qy, cs, sc, si, d9, i9, dmax, imax);
        } else {
            if (cy - r >= 0)
                for (int X = xlo; X <= xhi; X++)
                    scan_cell(X, cy - r, qx, qy, cs, sc, si, d9, i9, dmax, imax);
            if (cy + r <= GRID - 1)
                for (int X = xlo; X <= xhi; X++)
                    scan_cell(X, cy + r, qx, qy, cs, sc, si, d9, i9, dmax, imax);
            const int yl = max(cy - r + 1, 0), yh = min(cy + r - 1, GRID - 1);
            if (cx - r >= 0)
                for (int Y = yl; Y <= yh; Y++)
                    scan_cell(cx - r, Y, qx, qy, cs, sc, si, d9, i9, dmax, imax);
            if (cx + r <= GRID - 1)
                for (int Y = yl; Y <= yh; Y++)
                    scan_cell(cx + r, Y, qx, qy, cs, sc, si, d9, i9, dmax, imax);
        }
        const float rs = r * CELLSZ;
        if (rs * rs >= dmax) break;
    }
    #pragma unroll
    for (int j = 0; j < KNN; j++) g_nn[(size_t)q * KNN + j] = i9[j];
}

// ===========================================================================
// Fused launch: blocks [0,32) = kNN; blocks [32, 800) = QKV GEMM (MODE 2).
// ===========================================================================
#define KNN_BLOCKS 32

__global__ void __launch_bounds__(256, 2) qkv_knn_kernel(const float* __restrict__ coords)
{
    extern __shared__ __align__(128) unsigned char smem[];
    if (blockIdx.x < KNN_BLOCKS) {
        knn_query(coords, blockIdx.x * 256 + threadIdx.x);
    } else {
        const int idx = blockIdx.x - KNN_BLOCKS;
        gemm_body_bf16<2>(g_xb, g_wqb, nullptr, 3 * DMODEL, DMODEL, nullptr, nullptr,
                          (idx / 12) * 128, (idx % 12) * 128, smem);
    }
}

__global__ void __launch_bounds__(256, 2) proj_kernel(
    float* __restrict__ C, const float* __restrict__ bias, const float* __restrict__ resid)
{
    extern __shared__ __align__(128) unsigned char smem[];
    gemm_body_bf16<1>(g_attnb, g_wpb, C, DMODEL, DMODEL, bias, resid,
                      blockIdx.y * 128, blockIdx.x * 128, smem);
}

// ---------------------------------------------------------------------------
// Attention over 9 neighbors (Q fp32, K/V bf16), fused exact-erf GELU,
// bf16 output. One block per token, one warp per head, 2 elems per lane.
// ---------------------------------------------------------------------------
__global__ void __launch_bounds__(256) attn_kernel()
{
    const int r    = blockIdx.x;
    const int b    = r >> 12;
    const int h    = threadIdx.x >> 5;
    const int lane = threadIdx.x & 31;

    __shared__ int idx[KNN];
    if (threadIdx.x < KNN)
        idx[threadIdx.x] = (b << 12) + g_nn[(size_t)r * KNN + threadIdx.x];
    __syncthreads();

    const float2 qv = *(const float2*)(g_q + (size_t)r * DMODEL + h * HDIM + lane * 2);

    float logit[KNN];
    #pragma unroll
    for (int j = 0; j < KNN; j++) {
        const __nv_bfloat162 kb = *(const __nv_bfloat162*)
            (g_kvb + (size_t)idx[j] * (2 * DMODEL) + h * HDIM + lane * 2);
        const float2 kv = __bfloat1622float2(kb);
        float p = qv.x * kv.x + qv.y * kv.y;
        #pragma unroll
        for (int s = 16; s; s >>= 1) p += __shfl_xor_sync(0xffffffffu, p, s);
        logit[j] = p * 0.125f;
    }

    float mx = logit[0];
    #pragma unroll
    for (int j = 1; j < KNN; j++) mx = fmaxf(mx, logit[j]);
    float sum = 0.f;
    #pragma unroll
    for (int j = 0; j < KNN; j++) { logit[j] = __expf(logit[j] - mx); sum += logit[j]; }
    const float inv = 1.f / sum;

    float2 acc = make_float2(0.f, 0.f);
    #pragma unroll
    for (int j = 0; j < KNN; j++) {
        const __nv_bfloat162 vb = *(const __nv_bfloat162*)
            (g_kvb + (size_t)idx[j] * (2 * DMODEL) + DMODEL + h * HDIM + lane * 2);
        const float2 vv = __bfloat1622float2(vb);
        const float w = logit[j] * inv;
        acc.x = fmaf(w, vv.x, acc.x);
        acc.y = fmaf(w, vv.y, acc.y);
    }

    acc.x = 0.5f * acc.x * (1.f + erff(acc.x * 0.70710678118654752f));
    acc.y = 0.5f * acc.y * (1.f + erff(acc.y * 0.70710678118654752f));

    *(__nv_bfloat162*)(g_attnb + (size_t)r * DMODEL + h * HDIM + lane * 2)
        = __floats2bfloat162_rn(acc.x, acc.y);
}

// ---------------------------------------------------------------------------
// kernel_launch: x, coords, w_qkv, w_proj, b_proj  ->  out (fp32, B*N*D)
// ---------------------------------------------------------------------------
extern "C" void kernel_launch(void* const* d_in, const int* in_sizes, int n_in,
                              void* d_out, int out_size)
{
    const float* x      = (const float*)d_in[0];
    const float* coords = (const float*)d_in[1];
    const float* w_qkv  = (const float*)d_in[2];
    const float* w_proj = (const float*)d_in[3];
    const float* b_proj = (const float*)d_in[4];
    float* out = (float*)d_out;

    constexpr int SMEM = 65536;   // 4-stage ring: 4 x 16KB
    cudaFuncSetAttribute(qkv_knn_kernel, cudaFuncAttributeMaxDynamicSharedMemorySize, SMEM);
    cudaFuncSetAttribute(proj_kernel,    cudaFuncAttributeMaxDynamicSharedMemorySize, SMEM);

    // 1) grid build (2 blocks) + fp32->bf16 conversion
    prep_kernel<<<BATCH + 640, 1024>>>(x, coords, w_qkv, w_proj);

    // 2) kNN query (32 blocks, first) + QKV GEMM (768 blocks)
    qkv_knn_kernel<<<KNN_BLOCKS + 768, 256, SMEM>>>(coords);

    // 3) neighbor attention + GELU (bf16 out)
    attn_kernel<<<MROWS, 256>>>();

    // 4) output projection + bias + residual
    {
        dim3 grid(DMODEL / 128, MROWS / 128);
        proj_kernel<<<grid, 256, SMEM>>>(out, b_proj, x);
    }
}